// round 5
// baseline (speedup 1.0000x reference)
#include <cuda_runtime.h>
#include <math.h>

#define HH 224
#define WW 224
#define BB 2
#define PP 2048
#define FF 256
#define SIGMA_F 0.0003f
#define INV_SIGMA 3333.3333333f
#define D2CUT (88.0f * SIGMA_F)      // exp underflow threshold (matches fp32 reference)
#define MARGIN 0.16248077f           // sqrt(D2CUT)
#define NV4 10

// Face data layout in g_face4 (float4 x 10 per face):
// [0]: x2, y2, A0, B0
// [1]: A1, B1, z0, z1
// [2]: z2, k12, k20, k01
// [3]: x0, y0, x1, y1
// [4]: e01x, e01y, i01, 0
// [5]: e12x, e12y, i12, 0
// [6]: e20x, e20y, i20, 0
// [7..9]: colors
__device__ float4 g_face4[BB][FF][NV4];
__device__ float4 g_bbox[BB][FF];
__device__ int    g_cnt[BB];

// ---------------------------------------------------------------------------
// Prep: one block per batch (256 threads = 256 faces).
// ---------------------------------------------------------------------------
__global__ void vcr_prep_kernel(const float* __restrict__ pts,
                                const int*   __restrict__ faces,
                                const float* __restrict__ rot,
                                const float* __restrict__ pos,
                                const float* __restrict__ proj,
                                const float* __restrict__ cols,
                                float* __restrict__ out)
{
    int b = blockIdx.x;
    int f = threadIdx.x;

    float R0 = rot[b*9+0], R1 = rot[b*9+1], R2 = rot[b*9+2];
    float R3 = rot[b*9+3], R4 = rot[b*9+4], R5 = rot[b*9+5];
    float R6 = rot[b*9+6], R7 = rot[b*9+7], R8 = rot[b*9+8];
    float cpx = pos[b*3+0], cpy = pos[b*3+1], cpz = pos[b*3+2];
    float pr0 = proj[0], pr1 = proj[1], pr2 = proj[2];

    int vi[3] = { faces[f*3+0], faces[f*3+1], faces[f*3+2] };

    float Px[3], Py[3], Pz[3], Qx[3], Qy[3], C[3][3];
    #pragma unroll
    for (int k = 0; k < 3; k++) {
        const float* pp = pts + ((size_t)b * PP + vi[k]) * 3;
        float dx = pp[0]-cpx, dy = pp[1]-cpy, dz = pp[2]-cpz;
        float cx = R0*dx + R1*dy + R2*dz;
        float cy = R3*dx + R4*dy + R5*dz;
        float cz = R6*dx + R7*dy + R8*dz;
        Px[k]=cx; Py[k]=cy; Pz[k]=cz;
        float zz = cz * pr2;
        Qx[k] = (cx*pr0)/zz;
        Qy[k] = (cy*pr1)/zz;
        const float* cc = cols + ((size_t)b * PP + vi[k]) * 3;
        C[k][0]=cc[0]; C[k][1]=cc[1]; C[k][2]=cc[2];
    }

    float ux=Px[1]-Px[0], uy=Py[1]-Py[0], uz=Pz[1]-Pz[0];
    float vx=Px[2]-Px[0], vy=Py[2]-Py[0], vz=Pz[2]-Pz[0];
    float nx = uy*vz - uz*vy;
    float ny = uz*vx - ux*vz;
    float nz = ux*vy - uy*vx;
    float inv = 1.0f / sqrtf(nx*nx + ny*ny + nz*nz + 1e-10f);

    size_t noff = (size_t)BB*HH*WW*3 + (size_t)BB*HH*WW + ((size_t)b*FF + f)*3;
    out[noff+0] = nx*inv;
    out[noff+1] = ny*inv;
    out[noff+2] = nz*inv;

    bool front = (nz > 0.0f);

    // order-preserving compaction (argmax tie order must match reference)
    __shared__ int warp_off[9];
    unsigned mask = __ballot_sync(0xffffffffu, front);
    int lane = threadIdx.x & 31, wid = threadIdx.x >> 5;
    if (lane == 0) warp_off[wid] = __popc(mask);
    __syncthreads();
    if (threadIdx.x == 0) {
        int s = 0;
        for (int i = 0; i < 8; i++) { int t = warp_off[i]; warp_off[i] = s; s += t; }
        g_cnt[b] = s;
    }
    __syncthreads();
    if (!front) return;
    int slot = warp_off[wid] + __popc(mask & ((1u << lane) - 1u));

    float denom = (Qy[1]-Qy[2])*(Qx[0]-Qx[2]) + (Qx[2]-Qx[1])*(Qy[0]-Qy[2]);
    if (fabsf(denom) < 1e-10f) denom = 1e-10f;
    float invden = 1.0f / denom;
    float den2 = denom * denom;

    float e01x = Qx[1]-Qx[0], e01y = Qy[1]-Qy[0];
    float e12x = Qx[2]-Qx[1], e12y = Qy[2]-Qy[1];
    float e20x = Qx[0]-Qx[2], e20y = Qy[0]-Qy[2];
    float i01 = 1.0f/(e01x*e01x + e01y*e01y + 1e-10f);
    float i12 = 1.0f/(e12x*e12x + e12y*e12y + 1e-10f);
    float i20 = 1.0f/(e20x*e20x + e20y*e20y + 1e-10f);

    float4* dst = &g_face4[b][slot][0];
    dst[0] = make_float4(Qx[2], Qy[2], (Qy[1]-Qy[2])*invden, (Qx[2]-Qx[1])*invden);
    dst[1] = make_float4((Qy[2]-Qy[0])*invden, (Qx[0]-Qx[2])*invden, Pz[0], Pz[1]);
    dst[2] = make_float4(Pz[2], den2*i12, den2*i20, den2*i01);
    dst[3] = make_float4(Qx[0], Qy[0], Qx[1], Qy[1]);
    dst[4] = make_float4(e01x, e01y, i01, 0.0f);
    dst[5] = make_float4(e12x, e12y, i12, 0.0f);
    dst[6] = make_float4(e20x, e20y, i20, 0.0f);
    dst[7] = make_float4(C[0][0], C[0][1], C[0][2], C[1][0]);
    dst[8] = make_float4(C[1][1], C[1][2], C[2][0], C[2][1]);
    dst[9] = make_float4(C[2][2], 0.0f, 0.0f, 0.0f);

    g_bbox[b][slot] = make_float4(
        fminf(Qx[0], fminf(Qx[1], Qx[2])),
        fminf(Qy[0], fminf(Qy[1], Qy[2])),
        fmaxf(Qx[0], fmaxf(Qx[1], Qx[2])),
        fmaxf(Qy[0], fmaxf(Qy[1], Qy[2])));
}

// ---------------------------------------------------------------------------
// Render: 64 threads/block, 1 pixel/thread, 16x4 tile.
// Warp 0 does the bbox cull (index list only); face data via uniform __ldg.
// ---------------------------------------------------------------------------
__global__ void __launch_bounds__(64) vcr_render_kernel(float* __restrict__ out)
{
    int b = blockIdx.z;
    __shared__ int slist[FF];
    __shared__ int sm;

    int tx0 = blockIdx.x * 16;
    int ty0 = blockIdx.y * 4;
    float txmin = (2.0f*tx0 + 1.0f) * (1.0f/WW) - 1.0f;
    float txmax = (2.0f*(tx0+15) + 1.0f) * (1.0f/WW) - 1.0f;
    float tymax = 1.0f - (2.0f*ty0 + 1.0f) * (1.0f/HH);
    float tymin = 1.0f - (2.0f*(ty0+3) + 1.0f) * (1.0f/HH);

    if (threadIdx.x < 32) {
        int lane = threadIdx.x;
        int cnt = g_cnt[b];
        int base = 0;
        for (int r = 0; r < FF; r += 32) {
            int f = r + lane;
            bool keep = false;
            if (f < cnt) {
                float4 bb = __ldg(&g_bbox[b][f]);
                keep = (bb.x - MARGIN <= txmax) & (bb.z + MARGIN >= txmin) &
                       (bb.y - MARGIN <= tymax) & (bb.w + MARGIN >= tymin);
            }
            unsigned mask = __ballot_sync(0xffffffffu, keep);
            if (keep) slist[base + __popc(mask & ((1u << lane) - 1u))] = f;
            base += __popc(mask);
        }
        if (lane == 0) sm = base;
    }
    __syncthreads();
    int m = sm;

    int x = tx0 + (threadIdx.x & 15);
    int y = ty0 + (threadIdx.x >> 4);
    float px = (2.0f*x + 1.0f) * (1.0f/WW) - 1.0f;
    float py = 1.0f - (2.0f*y + 1.0f) * (1.0f/HH);

    const float IN_F = 1.0f - (1.0f - 1e-7f);   // exact (Sterbenz)

    float best = -1e10f;
    int   bi   = -1;
    float bl0 = 0.0f, bl1 = 0.0f, bl2 = 0.0f;
    float prod = 1.0f;

    #pragma unroll 2
    for (int i = 0; i < m; i++) {
        int f = slist[i];
        const float4* fp = &g_face4[b][f][0];
        float4 v0 = __ldg(fp + 0);
        float4 v1 = __ldg(fp + 1);
        float4 v2 = __ldg(fp + 2);

        float dx = px - v0.x, dy = py - v0.y;
        float l0 = fmaf(v0.z, dx, v0.w * dy);
        float l1 = fmaf(v1.x, dx, v1.y * dy);
        float l2 = 1.0f - l0 - l1;

        if (fminf(l0, fminf(l1, l2)) >= 0.0f) {
            float z = l0*v1.z + l1*v1.w + l2*v2.x;
            if (z > best) { best = z; bi = f; bl0 = l0; bl1 = l1; bl2 = l2; }
            prod *= IN_F;
        } else {
            float lb2 = 0.0f;
            if (l0 < 0.0f) lb2 = l0*l0*v2.y;
            if (l1 < 0.0f) lb2 = fmaxf(lb2, l1*l1*v2.z);
            if (l2 < 0.0f) lb2 = fmaxf(lb2, l2*l2*v2.w);
            if (lb2 < D2CUT) {
                float4 v3 = __ldg(fp + 3);
                float4 v4 = __ldg(fp + 4);
                float4 v5 = __ldg(fp + 5);
                float4 v6 = __ldg(fp + 6);

                float pax = px - v3.x, pay = py - v3.y;     // from v0
                float t = fminf(fmaxf((pax*v4.x + pay*v4.y)*v4.z, 0.0f), 1.0f);
                float ddx = pax - t*v4.x, ddy = pay - t*v4.y;
                float d2 = ddx*ddx + ddy*ddy;

                pax = px - v3.z; pay = py - v3.w;           // from v1
                t = fminf(fmaxf((pax*v5.x + pay*v5.y)*v5.z, 0.0f), 1.0f);
                ddx = pax - t*v5.x; ddy = pay - t*v5.y;
                d2 = fminf(d2, ddx*ddx + ddy*ddy);

                pax = px - v0.x; pay = py - v0.y;           // from v2
                t = fminf(fmaxf((pax*v6.x + pay*v6.y)*v6.z, 0.0f), 1.0f);
                ddx = pax - t*v6.x; ddy = pay - t*v6.y;
                d2 = fminf(d2, ddx*ddx + ddy*ddy);

                if (d2 < D2CUT) {
                    float p = __expf(-d2 * INV_SIGMA) * (1.0f - 1e-7f);
                    prod *= fmaxf(1.0f - p, 0.0f);
                }
            }
        }
    }

    float r = 0.0f, g = 0.0f, bcol = 0.0f;
    if (bi >= 0) {
        const float4* fp = &g_face4[b][bi][7];
        float4 c0 = __ldg(fp + 0);
        float4 c1 = __ldg(fp + 1);
        float4 c2 = __ldg(fp + 2);
        r    = bl0*c0.x + bl1*c0.w + bl2*c1.z;
        g    = bl0*c0.y + bl1*c1.x + bl2*c1.w;
        bcol = bl0*c0.z + bl1*c1.y + bl2*c2.x;
    }

    size_t ro = ((size_t)(b*HH + y)*WW + x)*3;
    out[ro+0] = r;
    out[ro+1] = g;
    out[ro+2] = bcol;
    size_t po = (size_t)BB*HH*WW*3 + (size_t)(b*HH + y)*WW + x;
    out[po] = 1.0f - prod;
}

extern "C" void kernel_launch(void* const* d_in, const int* in_sizes, int n_in,
                              void* d_out, int out_size)
{
    const float* pts   = (const float*)d_in[0];
    const int*   faces = (const int*)d_in[1];
    const float* rot   = (const float*)d_in[2];
    const float* pos   = (const float*)d_in[3];
    const float* proj  = (const float*)d_in[4];
    const float* cols  = (const float*)d_in[5];
    float* out = (float*)d_out;

    vcr_prep_kernel<<<BB, FF>>>(pts, faces, rot, pos, proj, cols, out);

    dim3 grid(WW/16, HH/4, BB);   // 14 x 56 x 2 = 1568 blocks
    vcr_render_kernel<<<grid, 64>>>(out);
}

// round 6
// speedup vs baseline: 1.0065x; 1.0065x over previous
#include <cuda_runtime.h>
#include <math.h>

#define HH 224
#define WW 224
#define BB 2
#define PP 2048
#define FF 256
#define SIGMA_F 0.0003f
#define INV_SIGMA 3333.3333333f
#define D2CUT (88.0f * SIGMA_F)      // exp underflow threshold (matches fp32 reference)
#define MARGIN 0.16248077f           // sqrt(D2CUT)
#define NV4 10
#define TILES_X 14                   // 16-px wide
#define TILES_Y 56                   // 4-px tall
#define NTILES (TILES_X * TILES_Y * BB)   // 1568

// Face data layout in g_face4 (float4 x 10 per face):
// [0]: x2, y2, A0, B0
// [1]: A1, B1, z0, z1
// [2]: z2, k12, k20, k01
// [3]: x0, y0, x1, y1
// [4]: e01x, e01y, i01, 0
// [5]: e12x, e12y, i12, 0
// [6]: e20x, e20y, i20, 0
// [7..9]: colors
__device__ float4 g_face4[BB][FF][NV4];
__device__ float4 g_bbox[BB][FF];
__device__ int    g_cnt[BB];

// ---------------------------------------------------------------------------
// Prep: one block per batch (256 threads = 256 faces).
// ---------------------------------------------------------------------------
__global__ void vcr_prep_kernel(const float* __restrict__ pts,
                                const int*   __restrict__ faces,
                                const float* __restrict__ rot,
                                const float* __restrict__ pos,
                                const float* __restrict__ proj,
                                const float* __restrict__ cols,
                                float* __restrict__ out)
{
    int b = blockIdx.x;
    int f = threadIdx.x;

    float R0 = rot[b*9+0], R1 = rot[b*9+1], R2 = rot[b*9+2];
    float R3 = rot[b*9+3], R4 = rot[b*9+4], R5 = rot[b*9+5];
    float R6 = rot[b*9+6], R7 = rot[b*9+7], R8 = rot[b*9+8];
    float cpx = pos[b*3+0], cpy = pos[b*3+1], cpz = pos[b*3+2];
    float pr0 = proj[0], pr1 = proj[1], pr2 = proj[2];

    int vi[3] = { faces[f*3+0], faces[f*3+1], faces[f*3+2] };

    float Px[3], Py[3], Pz[3], Qx[3], Qy[3], C[3][3];
    #pragma unroll
    for (int k = 0; k < 3; k++) {
        const float* pp = pts + ((size_t)b * PP + vi[k]) * 3;
        float dx = pp[0]-cpx, dy = pp[1]-cpy, dz = pp[2]-cpz;
        float cx = R0*dx + R1*dy + R2*dz;
        float cy = R3*dx + R4*dy + R5*dz;
        float cz = R6*dx + R7*dy + R8*dz;
        Px[k]=cx; Py[k]=cy; Pz[k]=cz;
        float zz = cz * pr2;
        Qx[k] = (cx*pr0)/zz;
        Qy[k] = (cy*pr1)/zz;
        const float* cc = cols + ((size_t)b * PP + vi[k]) * 3;
        C[k][0]=cc[0]; C[k][1]=cc[1]; C[k][2]=cc[2];
    }

    float ux=Px[1]-Px[0], uy=Py[1]-Py[0], uz=Pz[1]-Pz[0];
    float vx=Px[2]-Px[0], vy=Py[2]-Py[0], vz=Pz[2]-Pz[0];
    float nx = uy*vz - uz*vy;
    float ny = uz*vx - ux*vz;
    float nz = ux*vy - uy*vx;
    float inv = 1.0f / sqrtf(nx*nx + ny*ny + nz*nz + 1e-10f);

    size_t noff = (size_t)BB*HH*WW*3 + (size_t)BB*HH*WW + ((size_t)b*FF + f)*3;
    out[noff+0] = nx*inv;
    out[noff+1] = ny*inv;
    out[noff+2] = nz*inv;

    bool front = (nz > 0.0f);

    // order-preserving compaction (argmax tie order must match reference)
    __shared__ int warp_off[9];
    unsigned mask = __ballot_sync(0xffffffffu, front);
    int lane = threadIdx.x & 31, wid = threadIdx.x >> 5;
    if (lane == 0) warp_off[wid] = __popc(mask);
    __syncthreads();
    if (threadIdx.x == 0) {
        int s = 0;
        for (int i = 0; i < 8; i++) { int t = warp_off[i]; warp_off[i] = s; s += t; }
        g_cnt[b] = s;
    }
    __syncthreads();
    if (!front) return;
    int slot = warp_off[wid] + __popc(mask & ((1u << lane) - 1u));

    float denom = (Qy[1]-Qy[2])*(Qx[0]-Qx[2]) + (Qx[2]-Qx[1])*(Qy[0]-Qy[2]);
    if (fabsf(denom) < 1e-10f) denom = 1e-10f;
    float invden = 1.0f / denom;
    float den2 = denom * denom;

    float e01x = Qx[1]-Qx[0], e01y = Qy[1]-Qy[0];
    float e12x = Qx[2]-Qx[1], e12y = Qy[2]-Qy[1];
    float e20x = Qx[0]-Qx[2], e20y = Qy[0]-Qy[2];
    float i01 = 1.0f/(e01x*e01x + e01y*e01y + 1e-10f);
    float i12 = 1.0f/(e12x*e12x + e12y*e12y + 1e-10f);
    float i20 = 1.0f/(e20x*e20x + e20y*e20y + 1e-10f);

    float4* dst = &g_face4[b][slot][0];
    dst[0] = make_float4(Qx[2], Qy[2], (Qy[1]-Qy[2])*invden, (Qx[2]-Qx[1])*invden);
    dst[1] = make_float4((Qy[2]-Qy[0])*invden, (Qx[0]-Qx[2])*invden, Pz[0], Pz[1]);
    dst[2] = make_float4(Pz[2], den2*i12, den2*i20, den2*i01);
    dst[3] = make_float4(Qx[0], Qy[0], Qx[1], Qy[1]);
    dst[4] = make_float4(e01x, e01y, i01, 0.0f);
    dst[5] = make_float4(e12x, e12y, i12, 0.0f);
    dst[6] = make_float4(e20x, e20y, i20, 0.0f);
    dst[7] = make_float4(C[0][0], C[0][1], C[0][2], C[1][0]);
    dst[8] = make_float4(C[1][1], C[1][2], C[2][0], C[2][1]);
    dst[9] = make_float4(C[2][2], 0.0f, 0.0f, 0.0f);

    g_bbox[b][slot] = make_float4(
        fminf(Qx[0], fminf(Qx[1], Qx[2])),
        fminf(Qy[0], fminf(Qy[1], Qy[2])),
        fmaxf(Qx[0], fmaxf(Qx[1], Qx[2])),
        fmaxf(Qy[0], fmaxf(Qy[1], Qy[2])));
}

// ---------------------------------------------------------------------------
// Render: 128-thread blocks split into two independent 64-thread groups.
// Group g renders one 16x4 tile; group tiles are mirror-paired for balance.
// Per-group: single-warp bbox cull -> compact hot data into smem ->
// sequential inner loop. Edge/color data via __ldg (rare paths).
// ---------------------------------------------------------------------------
__global__ void __launch_bounds__(128) vcr_render_kernel(float* __restrict__ out)
{
    __shared__ float4 sf_hot[2][FF * 3];
    __shared__ int    slist[2][FF];
    __shared__ int    sm_cnt[2];

    int g    = threadIdx.x >> 6;          // group 0/1
    int q    = threadIdx.x & 63;          // thread-in-group
    int bar  = g + 1;                     // named barrier id

    int tile = (g == 0) ? blockIdx.x : (NTILES - 1 - blockIdx.x);
    int tx   = tile % TILES_X;
    int rest = tile / TILES_X;
    int ty   = rest % TILES_Y;
    int bm   = rest / TILES_Y;

    int tx0 = tx * 16;
    int ty0 = ty * 4;
    float txmin = (2.0f*tx0 + 1.0f) * (1.0f/WW) - 1.0f;
    float txmax = (2.0f*(tx0+15) + 1.0f) * (1.0f/WW) - 1.0f;
    float tymax = 1.0f - (2.0f*ty0 + 1.0f) * (1.0f/HH);
    float tymin = 1.0f - (2.0f*(ty0+3) + 1.0f) * (1.0f/HH);

    // single-warp cull (first warp of the group), order-preserving
    if (q < 32) {
        int lane = q;
        int cnt = g_cnt[bm];
        int base = 0;
        for (int r = 0; r < FF; r += 32) {
            int f = r + lane;
            bool keep = false;
            if (f < cnt) {
                float4 bb = __ldg(&g_bbox[bm][f]);
                keep = (bb.x - MARGIN <= txmax) & (bb.z + MARGIN >= txmin) &
                       (bb.y - MARGIN <= tymax) & (bb.w + MARGIN >= tymin);
            }
            unsigned mask = __ballot_sync(0xffffffffu, keep);
            if (keep) slist[g][base + __popc(mask & ((1u << lane) - 1u))] = f;
            base += __popc(mask);
        }
        if (lane == 0) sm_cnt[g] = base;
    }
    asm volatile("bar.sync %0, 64;" :: "r"(bar) : "memory");
    int m = sm_cnt[g];

    // compact hot data into smem (sequential for the loop)
    for (int i = q; i < m * 3; i += 64) {
        int li = i / 3, k = i - li * 3;
        sf_hot[g][i] = __ldg(&g_face4[bm][slist[g][li]][k]);
    }
    asm volatile("bar.sync %0, 64;" :: "r"(bar) : "memory");

    int x = tx0 + (q & 15);
    int y = ty0 + (q >> 4);
    float px = (2.0f*x + 1.0f) * (1.0f/WW) - 1.0f;
    float py = 1.0f - (2.0f*y + 1.0f) * (1.0f/HH);

    const float IN_F = 1.0f - (1.0f - 1e-7f);   // exact (Sterbenz)

    float best = -1e10f;
    int   bi   = -1;                             // list position of winner
    float bl0 = 0.0f, bl1 = 0.0f, bl2 = 0.0f;
    float prod = 1.0f;

    #pragma unroll 2
    for (int i = 0; i < m; i++) {
        float4 v0 = sf_hot[g][i*3+0];
        float4 v1 = sf_hot[g][i*3+1];
        float4 v2 = sf_hot[g][i*3+2];

        float dx = px - v0.x, dy = py - v0.y;
        float l0 = fmaf(v0.z, dx, v0.w * dy);
        float l1 = fmaf(v1.x, dx, v1.y * dy);
        float l2 = 1.0f - l0 - l1;

        if (fminf(l0, fminf(l1, l2)) >= 0.0f) {
            float z = l0*v1.z + l1*v1.w + l2*v2.x;
            if (z > best) { best = z; bi = i; bl0 = l0; bl1 = l1; bl2 = l2; }
            prod *= IN_F;
        } else {
            float lb2 = 0.0f;
            if (l0 < 0.0f) lb2 = l0*l0*v2.y;
            if (l1 < 0.0f) lb2 = fmaxf(lb2, l1*l1*v2.z);
            if (l2 < 0.0f) lb2 = fmaxf(lb2, l2*l2*v2.w);
            if (lb2 < D2CUT) {
                int f = slist[g][i];
                const float4* fp = &g_face4[bm][f][0];
                float4 v3 = __ldg(fp + 3);
                float4 v4 = __ldg(fp + 4);
                float4 v5 = __ldg(fp + 5);
                float4 v6 = __ldg(fp + 6);

                float pax = px - v3.x, pay = py - v3.y;     // from v0
                float t = fminf(fmaxf((pax*v4.x + pay*v4.y)*v4.z, 0.0f), 1.0f);
                float ddx = pax - t*v4.x, ddy = pay - t*v4.y;
                float d2 = ddx*ddx + ddy*ddy;

                pax = px - v3.z; pay = py - v3.w;           // from v1
                t = fminf(fmaxf((pax*v5.x + pay*v5.y)*v5.z, 0.0f), 1.0f);
                ddx = pax - t*v5.x; ddy = pay - t*v5.y;
                d2 = fminf(d2, ddx*ddx + ddy*ddy);

                pax = px - v0.x; pay = py - v0.y;           // from v2
                t = fminf(fmaxf((pax*v6.x + pay*v6.y)*v6.z, 0.0f), 1.0f);
                ddx = pax - t*v6.x; ddy = pay - t*v6.y;
                d2 = fminf(d2, ddx*ddx + ddy*ddy);

                if (d2 < D2CUT) {
                    float p = __expf(-d2 * INV_SIGMA) * (1.0f - 1e-7f);
                    prod *= fmaxf(1.0f - p, 0.0f);
                }
            }
        }
    }

    float r = 0.0f, gc = 0.0f, bcol = 0.0f;
    if (bi >= 0) {
        int f = slist[g][bi];
        const float4* fp = &g_face4[bm][f][7];
        float4 c0 = __ldg(fp + 0);
        float4 c1 = __ldg(fp + 1);
        float4 c2 = __ldg(fp + 2);
        r    = bl0*c0.x + bl1*c0.w + bl2*c1.z;
        gc   = bl0*c0.y + bl1*c1.x + bl2*c1.w;
        bcol = bl0*c0.z + bl1*c1.y + bl2*c2.x;
    }

    size_t ro = ((size_t)(bm*HH + y)*WW + x)*3;
    out[ro+0] = r;
    out[ro+1] = gc;
    out[ro+2] = bcol;
    size_t po = (size_t)BB*HH*WW*3 + (size_t)(bm*HH + y)*WW + x;
    out[po] = 1.0f - prod;
}

extern "C" void kernel_launch(void* const* d_in, const int* in_sizes, int n_in,
                              void* d_out, int out_size)
{
    const float* pts   = (const float*)d_in[0];
    const int*   faces = (const int*)d_in[1];
    const float* rot   = (const float*)d_in[2];
    const float* pos   = (const float*)d_in[3];
    const float* proj  = (const float*)d_in[4];
    const float* cols  = (const float*)d_in[5];
    float* out = (float*)d_out;

    vcr_prep_kernel<<<BB, FF>>>(pts, faces, rot, pos, proj, cols, out);

    vcr_render_kernel<<<NTILES / 2, 128>>>(out);   // 784 blocks
}

// round 9
// speedup vs baseline: 1.5824x; 1.5722x over previous
#include <cuda_runtime.h>
#include <math.h>

#define HH 224
#define WW 224
#define BB 2
#define PP 2048
#define FF 256
#define SIGMA_F 0.0003f
#define INV_SIGMA 3333.3333333f
#define D2CUT (88.0f * SIGMA_F)      // exp underflow threshold (matches fp32 reference)
#define MARGIN 0.16248077f           // sqrt(D2CUT)
#define NV4 10

// Face data layout in g_face4 (float4 x 10 per face):
// [0]: x2, y2, A0, B0
// [1]: A1, B1, z0, z1
// [2]: z2, k12, k20, k01
// [3]: x0, y0, x1, y1
// [4]: e01x, e01y, i01, 0
// [5]: e12x, e12y, i12, 0
// [6]: e20x, e20y, i20, 0
// [7..9]: colors
__device__ float4 g_face4[BB][FF][NV4];
__device__ float4 g_bbox[BB][FF];
__device__ int    g_cnt[BB];

// ---------------------------------------------------------------------------
// Prep: one block per batch (256 threads = 256 faces).
// ---------------------------------------------------------------------------
__global__ void vcr_prep_kernel(const float* __restrict__ pts,
                                const int*   __restrict__ faces,
                                const float* __restrict__ rot,
                                const float* __restrict__ pos,
                                const float* __restrict__ proj,
                                const float* __restrict__ cols,
                                float* __restrict__ out)
{
    int b = blockIdx.x;
    int f = threadIdx.x;

    float R0 = rot[b*9+0], R1 = rot[b*9+1], R2 = rot[b*9+2];
    float R3 = rot[b*9+3], R4 = rot[b*9+4], R5 = rot[b*9+5];
    float R6 = rot[b*9+6], R7 = rot[b*9+7], R8 = rot[b*9+8];
    float cpx = pos[b*3+0], cpy = pos[b*3+1], cpz = pos[b*3+2];
    float pr0 = proj[0], pr1 = proj[1], pr2 = proj[2];

    int vi[3] = { faces[f*3+0], faces[f*3+1], faces[f*3+2] };

    float Px[3], Py[3], Pz[3], Qx[3], Qy[3], C[3][3];
    #pragma unroll
    for (int k = 0; k < 3; k++) {
        const float* pp = pts + ((size_t)b * PP + vi[k]) * 3;
        float dx = pp[0]-cpx, dy = pp[1]-cpy, dz = pp[2]-cpz;
        float cx = R0*dx + R1*dy + R2*dz;
        float cy = R3*dx + R4*dy + R5*dz;
        float cz = R6*dx + R7*dy + R8*dz;
        Px[k]=cx; Py[k]=cy; Pz[k]=cz;
        float zz = cz * pr2;
        Qx[k] = (cx*pr0)/zz;
        Qy[k] = (cy*pr1)/zz;
        const float* cc = cols + ((size_t)b * PP + vi[k]) * 3;
        C[k][0]=cc[0]; C[k][1]=cc[1]; C[k][2]=cc[2];
    }

    float ux=Px[1]-Px[0], uy=Py[1]-Py[0], uz=Pz[1]-Pz[0];
    float vx=Px[2]-Px[0], vy=Py[2]-Py[0], vz=Pz[2]-Pz[0];
    float nx = uy*vz - uz*vy;
    float ny = uz*vx - ux*vz;
    float nz = ux*vy - uy*vx;
    float inv = 1.0f / sqrtf(nx*nx + ny*ny + nz*nz + 1e-10f);

    size_t noff = (size_t)BB*HH*WW*3 + (size_t)BB*HH*WW + ((size_t)b*FF + f)*3;
    out[noff+0] = nx*inv;
    out[noff+1] = ny*inv;
    out[noff+2] = nz*inv;

    bool front = (nz > 0.0f);

    // order-preserving compaction (argmax tie order must match reference)
    __shared__ int warp_off[9];
    unsigned mask = __ballot_sync(0xffffffffu, front);
    int lane = threadIdx.x & 31, wid = threadIdx.x >> 5;
    if (lane == 0) warp_off[wid] = __popc(mask);
    __syncthreads();
    if (threadIdx.x == 0) {
        int s = 0;
        for (int i = 0; i < 8; i++) { int t = warp_off[i]; warp_off[i] = s; s += t; }
        g_cnt[b] = s;
    }
    __syncthreads();
    if (!front) return;
    int slot = warp_off[wid] + __popc(mask & ((1u << lane) - 1u));

    float denom = (Qy[1]-Qy[2])*(Qx[0]-Qx[2]) + (Qx[2]-Qx[1])*(Qy[0]-Qy[2]);
    if (fabsf(denom) < 1e-10f) denom = 1e-10f;
    float invden = 1.0f / denom;
    float den2 = denom * denom;

    float e01x = Qx[1]-Qx[0], e01y = Qy[1]-Qy[0];
    float e12x = Qx[2]-Qx[1], e12y = Qy[2]-Qy[1];
    float e20x = Qx[0]-Qx[2], e20y = Qy[0]-Qy[2];
    float i01 = 1.0f/(e01x*e01x + e01y*e01y + 1e-10f);
    float i12 = 1.0f/(e12x*e12x + e12y*e12y + 1e-10f);
    float i20 = 1.0f/(e20x*e20x + e20y*e20y + 1e-10f);

    float4* dst = &g_face4[b][slot][0];
    dst[0] = make_float4(Qx[2], Qy[2], (Qy[1]-Qy[2])*invden, (Qx[2]-Qx[1])*invden);
    dst[1] = make_float4((Qy[2]-Qy[0])*invden, (Qx[0]-Qx[2])*invden, Pz[0], Pz[1]);
    dst[2] = make_float4(Pz[2], den2*i12, den2*i20, den2*i01);
    dst[3] = make_float4(Qx[0], Qy[0], Qx[1], Qy[1]);
    dst[4] = make_float4(e01x, e01y, i01, 0.0f);
    dst[5] = make_float4(e12x, e12y, i12, 0.0f);
    dst[6] = make_float4(e20x, e20y, i20, 0.0f);
    dst[7] = make_float4(C[0][0], C[0][1], C[0][2], C[1][0]);
    dst[8] = make_float4(C[1][1], C[1][2], C[2][0], C[2][1]);
    dst[9] = make_float4(C[2][2], 0.0f, 0.0f, 0.0f);

    g_bbox[b][slot] = make_float4(
        fminf(Qx[0], fminf(Qx[1], Qx[2])),
        fminf(Qy[0], fminf(Qy[1], Qy[2])),
        fmaxf(Qx[0], fmaxf(Qx[1], Qx[2])),
        fmaxf(Qy[0], fmaxf(Qy[1], Qy[2])));
}

// ---------------------------------------------------------------------------
// Render: 256 threads/block, 16x8 tile (128 px), 2 threads per pixel.
// Half 0 (tid<128) processes faces [0, m/2), half 1 [m/2, m); smem combine.
// ---------------------------------------------------------------------------
__global__ void __launch_bounds__(256) vcr_render_kernel(float* __restrict__ out)
{
    int b = blockIdx.z;
    __shared__ float4 sf_hot[FF * 3];
    __shared__ float4 sf_edge[FF * 4];
    __shared__ int    slist[FF];
    __shared__ int    warp_off[9];
    __shared__ int    sm_cnt;
    __shared__ float  cz[128], cl0[128], cl1[128], cl2[128], cprod[128];
    __shared__ int    cidx[128];

    int tx0 = blockIdx.x * 16;
    int ty0 = blockIdx.y * 8;
    float txmin = (2.0f*tx0 + 1.0f) * (1.0f/WW) - 1.0f;
    float txmax = (2.0f*(tx0+15) + 1.0f) * (1.0f/WW) - 1.0f;
    float tymax = 1.0f - (2.0f*ty0 + 1.0f) * (1.0f/HH);
    float tymin = 1.0f - (2.0f*(ty0+7) + 1.0f) * (1.0f/HH);

    // single-pass block cull over all 256 slots (order-preserving)
    {
        int f = threadIdx.x;
        int cnt = g_cnt[b];
        bool keep = false;
        if (f < cnt) {
            float4 bb = __ldg(&g_bbox[b][f]);
            keep = (bb.x - MARGIN <= txmax) & (bb.z + MARGIN >= txmin) &
                   (bb.y - MARGIN <= tymax) & (bb.w + MARGIN >= tymin);
        }
        unsigned mask = __ballot_sync(0xffffffffu, keep);
        int lane = threadIdx.x & 31, wid = threadIdx.x >> 5;
        if (lane == 0) warp_off[wid] = __popc(mask);
        __syncthreads();
        if (threadIdx.x == 0) {
            int s = 0;
            for (int i = 0; i < 8; i++) { int t = warp_off[i]; warp_off[i] = s; s += t; }
            sm_cnt = s;
        }
        __syncthreads();
        if (keep) slist[warp_off[wid] + __popc(mask & ((1u << lane) - 1u))] = f;
        __syncthreads();
    }
    int m = sm_cnt;

    // stage compacted face data (sequential layout for the loop)
    for (int i = threadIdx.x; i < m * 3; i += 256) {
        int li = i / 3, k = i - li * 3;
        sf_hot[i] = __ldg(&g_face4[b][slist[li]][k]);
    }
    for (int i = threadIdx.x; i < m * 4; i += 256) {
        int li = i >> 2, k = i & 3;
        sf_edge[i] = __ldg(&g_face4[b][slist[li]][3 + k]);
    }
    __syncthreads();

    int half = threadIdx.x >> 7;
    int q    = threadIdx.x & 127;
    int x = tx0 + (q & 15);
    int y = ty0 + (q >> 4);
    float px = (2.0f*x + 1.0f) * (1.0f/WW) - 1.0f;
    float py = 1.0f - (2.0f*y + 1.0f) * (1.0f/HH);

    const float IN_F = 1.0f - (1.0f - 1e-7f);   // exact (Sterbenz)

    int m0 = m >> 1;
    int ibeg = half ? m0 : 0;
    int iend = half ? m  : m0;

    float best = -1e10f;
    int   bi   = -1;
    float bl0 = 0.0f, bl1 = 0.0f, bl2 = 0.0f;
    float prod = 1.0f;

    #pragma unroll 2
    for (int i = ibeg; i < iend; i++) {
        float4 v0 = sf_hot[i*3+0];
        float4 v1 = sf_hot[i*3+1];
        float4 v2 = sf_hot[i*3+2];

        float dx = px - v0.x, dy = py - v0.y;
        float l0 = fmaf(v0.z, dx, v0.w * dy);
        float l1 = fmaf(v1.x, dx, v1.y * dy);
        float l2 = 1.0f - l0 - l1;

        if (fminf(l0, fminf(l1, l2)) >= 0.0f) {
            float z = l0*v1.z + l1*v1.w + l2*v2.x;
            if (z > best) { best = z; bi = i; bl0 = l0; bl1 = l1; bl2 = l2; }
            prod *= IN_F;
        } else {
            float lb2 = 0.0f;
            if (l0 < 0.0f) lb2 = l0*l0*v2.y;
            if (l1 < 0.0f) lb2 = fmaxf(lb2, l1*l1*v2.z);
            if (l2 < 0.0f) lb2 = fmaxf(lb2, l2*l2*v2.w);
            if (lb2 < D2CUT) {
                float4 v3 = sf_edge[i*4+0];
                float4 v4 = sf_edge[i*4+1];
                float4 v5 = sf_edge[i*4+2];
                float4 v6 = sf_edge[i*4+3];

                float pax = px - v3.x, pay = py - v3.y;     // from v0
                float t = fminf(fmaxf((pax*v4.x + pay*v4.y)*v4.z, 0.0f), 1.0f);
                float ddx = pax - t*v4.x, ddy = pay - t*v4.y;
                float d2 = ddx*ddx + ddy*ddy;

                pax = px - v3.z; pay = py - v3.w;           // from v1
                t = fminf(fmaxf((pax*v5.x + pay*v5.y)*v5.z, 0.0f), 1.0f);
                ddx = pax - t*v5.x; ddy = pay - t*v5.y;
                d2 = fminf(d2, ddx*ddx + ddy*ddy);

                pax = px - v0.x; pay = py - v0.y;           // from v2
                t = fminf(fmaxf((pax*v6.x + pay*v6.y)*v6.z, 0.0f), 1.0f);
                ddx = pax - t*v6.x; ddy = pay - t*v6.y;
                d2 = fminf(d2, ddx*ddx + ddy*ddy);

                if (d2 < D2CUT) {
                    float p = __expf(-d2 * INV_SIGMA) * (1.0f - 1e-7f);
                    prod *= fmaxf(1.0f - p, 0.0f);
                }
            }
        }
    }

    // combine halves: half 1 publishes, half 0 merges and writes
    if (half == 1) {
        cz[q] = best; cidx[q] = bi;
        cl0[q] = bl0; cl1[q] = bl1; cl2[q] = bl2;
        cprod[q] = prod;
    }
    __syncthreads();
    if (half == 0) {
        float z1 = cz[q];
        if (z1 > best) {            // strict: ties go to half 0 (lower indices)
            best = z1; bi = cidx[q];
            bl0 = cl0[q]; bl1 = cl1[q]; bl2 = cl2[q];
        }
        prod *= cprod[q];

        float r = 0.0f, g = 0.0f, bcol = 0.0f;
        if (bi >= 0) {
            const float4* fp = &g_face4[b][slist[bi]][7];
            float4 c0 = __ldg(fp + 0);
            float4 c1 = __ldg(fp + 1);
            float4 c2 = __ldg(fp + 2);
            r    = bl0*c0.x + bl1*c0.w + bl2*c1.z;
            g    = bl0*c0.y + bl1*c1.x + bl2*c1.w;
            bcol = bl0*c0.z + bl1*c1.y + bl2*c2.x;
        }

        size_t ro = ((size_t)(b*HH + y)*WW + x)*3;
        out[ro+0] = r;
        out[ro+1] = g;
        out[ro+2] = bcol;
        size_t po = (size_t)BB*HH*WW*3 + (size_t)(b*HH + y)*WW + x;
        out[po] = 1.0f - prod;
    }
}

extern "C" void kernel_launch(void* const* d_in, const int* in_sizes, int n_in,
                              void* d_out, int out_size)
{
    const float* pts   = (const float*)d_in[0];
    const int*   faces = (const int*)d_in[1];
    const float* rot   = (const float*)d_in[2];
    const float* pos   = (const float*)d_in[3];
    const float* proj  = (const float*)d_in[4];
    const float* cols  = (const float*)d_in[5];
    float* out = (float*)d_out;

    vcr_prep_kernel<<<BB, FF>>>(pts, faces, rot, pos, proj, cols, out);

    dim3 grid(WW/16, HH/8, BB);   // 14 x 28 x 2 = 784 blocks x 256 threads
    vcr_render_kernel<<<grid, 256>>>(out);
}